// round 4
// baseline (speedup 1.0000x reference)
#include <cuda_runtime.h>

// Problem constants
#define B_DIM 8
#define D_DIM 40
#define H_DIM 32
#define W_DIM 88
#define C_DIM 80
#define NX 256
#define NY 256
#define NCELL (NX * NY)          // 65536 cells per batch
#define CHUNK_B 2                // batches per chunk (scratch = 42 MB, fits L2)
#define N_CHUNKS (B_DIM / CHUNK_B)

// Reused channel-contiguous scratch: (CHUNK_B, NCELL, C) fp32 = 42 MB.
// .bss zero-init at module load; every transpose_zero pass restores it to
// zero, so it is zero at the start of every kernel_launch call/replay.
__device__ float g_scratch[(long long)CHUNK_B * NCELL * C_DIM];

// ---------------------------------------------------------------------------
// Scatter for one chunk of CHUNK_B batches.
// One block per (b_local, d, h) row of W=88 points.
// Phase 1: threads 0..87 compute the flat cell index (or -1) into smem.
// Phase 2: loop over (channel-quad q, w): 4 coalesced x loads, one
//          red.global.add.v4.f32 into L2-resident scratch.
// ---------------------------------------------------------------------------
__global__ void __launch_bounds__(256) scatter_kernel(
    const float* __restrict__ geom,   // (B, D, H, W, 3)
    const float* __restrict__ x,      // (B, D, C, H, W)
    int chunk)
{
    __shared__ int s_flat[W_DIM];

    const int bid     = blockIdx.x;              // 0 .. CHUNK_B*D*H-1
    const int b_local = bid / (D_DIM * H_DIM);
    const int rem     = bid - b_local * (D_DIM * H_DIM);
    const int d       = rem / H_DIM;
    const int h       = rem - d * H_DIM;
    const int b       = chunk * CHUNK_B + b_local;

    const int t = threadIdx.x;

    if (t < W_DIM) {
        const long long grow = ((long long)(b * D_DIM + d) * H_DIM + h) * W_DIM + t;
        const float* g = geom + grow * 3;
        const float gx = g[0];
        const float gy = g[1];
        const float gz = g[2];

        int flat = -1;
        if (gx >= -51.2f && gx < 51.2f &&
            gy >= -51.2f && gy < 51.2f &&
            gz >= -10.0f && gz < 10.0f) {
            // Match XLA: div-by-const lowered to mul-by-reciprocal (1/0.4 == 2.5f
            // exactly in fp32). add-then-mul cannot be FMA-contracted.
            const float rx = (gx + 51.2f) * 2.5f;
            const float ry = (gy + 51.2f) * 2.5f;
            int ix = (int)rx;
            int iy = (int)ry;
            ix = min(max(ix, 0), NX - 1);
            iy = min(max(iy, 0), NY - 1);
            flat = ix * NY + iy;
        }
        s_flat[t] = flat;
    }
    __syncthreads();

    // x index: (((b*D+d)*C + c)*H + h)*W + w
    const long long x_base = ((long long)(b * D_DIM + d) * C_DIM * H_DIM + h) * W_DIM;
    const int c_stride = H_DIM * W_DIM;                       // 2816
    float* const sb = g_scratch + (long long)b_local * NCELL * C_DIM;

    const int total = (C_DIM / 4) * W_DIM;   // 20 * 88 = 1760
    for (int idx = t; idx < total; idx += blockDim.x) {
        const int q = idx / W_DIM;           // channel quad 0..19
        const int w = idx - q * W_DIM;
        const int flat = s_flat[w];
        if (flat >= 0) {
            const float* xp = x + x_base + (long long)(q * 4) * c_stride + w;
            float v0 = __ldg(xp);
            float v1 = __ldg(xp + c_stride);
            float v2 = __ldg(xp + 2 * c_stride);
            float v3 = __ldg(xp + 3 * c_stride);
            float* dst = sb + (long long)flat * C_DIM + q * 4;  // 16B aligned
            asm volatile("red.global.add.v4.f32 [%0], {%1, %2, %3, %4};"
                         :: "l"(dst), "f"(v0), "f"(v1), "f"(v2), "f"(v3)
                         : "memory");
        }
    }
}

// ---------------------------------------------------------------------------
// Transpose scratch (CHUNK_B, NCELL, C) -> out (B, C, NCELL) for one chunk,
// AND re-zero the scratch in the same pass (each thread zeroes exactly the
// float4 it loaded — no race, no extra kernel). Scratch reads/zero-writes
// stay in L2; only the output store hits DRAM.
// ---------------------------------------------------------------------------
__global__ void __launch_bounds__(256) transpose_zero_kernel(
    float* __restrict__ out, int chunk)
{
    __shared__ float tile[64][81];

    const int blk     = blockIdx.x;            // 0 .. CHUNK_B*1024-1
    const int b_local = blk >> 10;
    const int tile0   = (blk & 1023) * 64;     // first cell of tile
    const int b       = chunk * CHUNK_B + b_local;
    const int t       = threadIdx.x;

    float4* src = (float4*)(g_scratch +
                  ((long long)b_local * NCELL + tile0) * C_DIM);

    // Load 64 cells * 20 float4 (coalesced), zero scratch behind us.
    #pragma unroll
    for (int i = t; i < 64 * 20; i += 256) {
        const int cell = i / 20;
        const int q    = i - cell * 20;
        float4 v = src[i];
        src[i] = make_float4(0.f, 0.f, 0.f, 0.f);
        tile[cell][q * 4 + 0] = v.x;
        tile[cell][q * 4 + 1] = v.y;
        tile[cell][q * 4 + 2] = v.z;
        tile[cell][q * 4 + 3] = v.w;
    }
    __syncthreads();

    // Store 80 channels * 16 cell-quads (coalesced float4).
    float* ob = out + (long long)b * C_DIM * NCELL + tile0;
    #pragma unroll
    for (int i = t; i < 80 * 16; i += 256) {
        const int c  = i / 16;
        const int cg = i - c * 16;
        float4 v;
        v.x = tile[cg * 4 + 0][c];
        v.y = tile[cg * 4 + 1][c];
        v.z = tile[cg * 4 + 2][c];
        v.w = tile[cg * 4 + 3][c];
        *(float4*)(ob + (long long)c * NCELL + cg * 4) = v;
    }
}

extern "C" void kernel_launch(void* const* d_in, const int* in_sizes, int n_in,
                              void* d_out, int out_size) {
    const float* geom = (const float*)d_in[0];   // (8,40,32,88,3)
    const float* x    = (const float*)d_in[1];   // (8,40,80,32,88)
    float* out        = (float*)d_out;           // (8,80,256,256)

    // Scratch is guaranteed zero here: .bss zero-init on first call, and every
    // transpose_zero_kernel pass restores it to zero thereafter.
    for (int chunk = 0; chunk < N_CHUNKS; chunk++) {
        scatter_kernel<<<CHUNK_B * D_DIM * H_DIM, 256>>>(geom, x, chunk);
        transpose_zero_kernel<<<CHUNK_B * (NCELL / 64), 256>>>(out, chunk);
    }
}